// round 9
// baseline (speedup 1.0000x reference)
#include <cuda_runtime.h>
#include <float.h>

#define NB     2
#define NN     8192
#define KNN    20
#define COUT   64
#define NCLASS 40
#define BN_EPS 1e-5f
#define EPT    8
#define NBLK   (8 * NB)     // total blocks in grid — all co-resident (1 wave)

// Scratch (no allocations allowed)
__device__ alignas(16) float  g_A[NB * NN];
__device__ alignas(16) float  g_B[NB * NN];
__device__ alignas(16) float4 g_pack[NB * NN];   // {x, dmin, dmax, 0}

// Software grid barrier state (sense-reversing; survives graph replays)
__device__ unsigned g_count = 0;
__device__ unsigned g_sense = 0;

__device__ __forceinline__ void grid_sync(unsigned& phase) {
    __threadfence();
    __syncthreads();
    phase ^= 1u;
    if (threadIdx.x == 0) {
        if (atomicAdd(&g_count, 1u) == NBLK - 1u) {
            atomicExch(&g_count, 0u);
            __threadfence();
            atomicExch(&g_sense, phase);
        } else {
            while (atomicAdd(&g_sense, 0u) != phase) { __nanosleep(64); }
        }
    }
    __syncthreads();
}

// ---------------------------------------------------------------------------
// Compare-exchange helpers — ALL register indices compile-time constant.
// Global bitonic rule: at stage k, element i merges ascending iff (i&k)==0.
// ---------------------------------------------------------------------------
__device__ __forceinline__ void ce(float& a, float& b, bool up) {
    float mn = fminf(a, b), mx = fmaxf(a, b);
    a = up ? mn : mx;
    b = up ? mx : mn;
}

__device__ __forceinline__ void reg_merge(float v[EPT], bool d) {
    ce(v[0], v[4], d); ce(v[1], v[5], d); ce(v[2], v[6], d); ce(v[3], v[7], d);
    ce(v[0], v[2], d); ce(v[1], v[3], d); ce(v[4], v[6], d); ce(v[5], v[7], d);
    ce(v[0], v[1], d); ce(v[2], v[3], d); ce(v[4], v[5], d); ce(v[6], v[7], d);
}

__device__ __forceinline__ void sort8(float v[EPT], bool d8) {
    ce(v[0], v[1], true);  ce(v[2], v[3], false);
    ce(v[4], v[5], true);  ce(v[6], v[7], false);
    ce(v[0], v[2], true);  ce(v[1], v[3], true);
    ce(v[4], v[6], false); ce(v[5], v[7], false);
    ce(v[0], v[1], true);  ce(v[2], v[3], true);
    ce(v[4], v[5], false); ce(v[6], v[7], false);
    reg_merge(v, d8);
}

__device__ __forceinline__ void warp_merge(float v[EPT], bool d, int xm_start, int t) {
    for (int xm = xm_start; xm >= 1; xm >>= 1) {
        bool lowup = (((t & xm) == 0) == d);
        #pragma unroll
        for (int m = 0; m < EPT; m++) {
            float pv = __shfl_xor_sync(0xffffffffu, v[m], xm);
            v[m] = lowup ? fminf(v[m], pv) : fmaxf(v[m], pv);
        }
    }
    reg_merge(v, d);
}

// smem substages j = jstart..256 (128-thread block), then intra-warp tail.
__device__ __forceinline__ void block_merge128(float v[EPT], float4* sA, int t,
                                               bool d, int jstart) {
    float4* sB = sA + 128;
    for (int j = jstart; j >= 256; j >>= 1) {
        sA[t] = make_float4(v[0], v[1], v[2], v[3]);
        sB[t] = make_float4(v[4], v[5], v[6], v[7]);
        __syncthreads();
        const int  pt    = t ^ (j >> 3);
        const bool lowup = (((t & (j >> 3)) == 0) == d);
        float4 pa = sA[pt], pb = sB[pt];
        v[0] = lowup ? fminf(v[0], pa.x) : fmaxf(v[0], pa.x);
        v[1] = lowup ? fminf(v[1], pa.y) : fmaxf(v[1], pa.y);
        v[2] = lowup ? fminf(v[2], pa.z) : fmaxf(v[2], pa.z);
        v[3] = lowup ? fminf(v[3], pa.w) : fmaxf(v[3], pa.w);
        v[4] = lowup ? fminf(v[4], pb.x) : fmaxf(v[4], pb.x);
        v[5] = lowup ? fminf(v[5], pb.y) : fmaxf(v[5], pb.y);
        v[6] = lowup ? fminf(v[6], pb.z) : fmaxf(v[6], pb.z);
        v[7] = lowup ? fminf(v[7], pb.w) : fmaxf(v[7], pb.w);
        __syncthreads();
    }
    warp_merge(v, d, 16, t);
}

__device__ __forceinline__ float4 f4ce(float4 a, float4 b, bool mn) {
    float4 r;
    r.x = mn ? fminf(a.x, b.x) : fmaxf(a.x, b.x);
    r.y = mn ? fminf(a.y, b.y) : fmaxf(a.y, b.y);
    r.z = mn ? fminf(a.z, b.z) : fmaxf(a.z, b.z);
    r.w = mn ? fminf(a.w, b.w) : fmaxf(a.w, b.w);
    return r;
}

__device__ __forceinline__ void store8(float* dstp, int base, const float v[EPT]) {
    float4* dst = (float4*)(dstp + base);
    dst[0] = make_float4(v[0], v[1], v[2], v[3]);
    dst[1] = make_float4(v[4], v[5], v[6], v[7]);
}

// ---------------------------------------------------------------------------
// THE kernel: all phases, separated by software grid barriers.
// grid (8, NB) x 128 threads, block (cx,b) owns 1024-chunk cx of batch b.
// ---------------------------------------------------------------------------
__global__ void __launch_bounds__(128, 1)
k_all(const float* __restrict__ x,      const float* __restrict__ conv_w,
      const float* __restrict__ gamma,  const float* __restrict__ beta,
      const float* __restrict__ mean,   const float* __restrict__ var,
      const float* __restrict__ lin_w,  float* __restrict__ out) {
    __shared__ float4 s4[256];
    __shared__ float  swin[1024 + 2 * (KNN - 1) + 2];
    __shared__ float  fx1[4][8], fx2[4][8], bx1[8], bx2[8];
    __shared__ unsigned sphase;
    const int t = threadIdx.x;
    const int cx = blockIdx.x, b = blockIdx.y;

    if (t == 0) sphase = atomicAdd(&g_sense, 0u);   // graph-replay-safe parity
    __syncthreads();
    unsigned phase = sphase;

    // ===== Phase A: sort chunk (k <= 1024), x -> g_A; zero d_out ============
    if (b == 0 && cx == 0 && t < NB * NCLASS) out[t] = 0.f;
    float v[EPT];
    { const float4* src = (const float4*)(x + b * NN + cx * 1024);
      float4 a = src[t * 2], c = src[t * 2 + 1];
      v[0]=a.x; v[1]=a.y; v[2]=a.z; v[3]=a.w;
      v[4]=c.x; v[5]=c.y; v[6]=c.z; v[7]=c.w; }
    sort8(v, (t & 1) == 0);
    for (int k = 16; k <= 256; k <<= 1)
        warp_merge(v, (t & (k >> 3)) == 0, k >> 4, t);
    block_merge128(v, s4, t, (t & 64) == 0, 256);    // k = 512
    block_merge128(v, s4, t, (cx & 1) == 0, 512);    // k = 1024
    store8(g_A, b * NN + cx * 1024 + t * EPT, v);
    grid_sync(phase);

    // ===== Phase B: k = 2048 butterfly, g_A -> g_B ===========================
    {
        const float4* src = (const float4*)(g_A + b * NN);
        const bool asc = ((cx >> 1) & 1) == 0;
        const bool km1 = asc == ((cx & 1) == 0);
        #pragma unroll
        for (int g = 0; g < 2; g++) {
            const int o = t * 2 + g;
            float4 r = f4ce(src[cx * 256 + o], src[(cx ^ 1) * 256 + o], km1);
            v[g*4+0]=r.x; v[g*4+1]=r.y; v[g*4+2]=r.z; v[g*4+3]=r.w;
        }
        block_merge128(v, s4, t, asc, 512);
        store8(g_B, b * NN + cx * 1024 + t * EPT, v);
    }
    grid_sync(phase);

    // ===== Phase C: k = 4096 butterfly, g_B -> g_A ===========================
    {
        const float4* src = (const float4*)(g_B + b * NN);
        const bool asc = ((cx >> 2) & 1) == 0;
        const bool km1 = asc == (((cx >> 1) & 1) == 0);
        const bool km2 = asc == ((cx & 1) == 0);
        #pragma unroll
        for (int g = 0; g < 2; g++) {
            const int o = t * 2 + g;
            float4 a0 = src[cx * 256 + o],       a1 = src[(cx ^ 1) * 256 + o];
            float4 a2 = src[(cx ^ 2) * 256 + o], a3 = src[(cx ^ 3) * 256 + o];
            float4 r = f4ce(f4ce(a0, a2, km1), f4ce(a1, a3, km1), km2);
            v[g*4+0]=r.x; v[g*4+1]=r.y; v[g*4+2]=r.z; v[g*4+3]=r.w;
        }
        block_merge128(v, s4, t, asc, 512);
        store8(g_A, b * NN + cx * 1024 + t * EPT, v);
    }
    grid_sync(phase);

    // ===== Phase D: k = 8192 butterfly (final, ascending), g_A -> g_B ========
    {
        const float4* src = (const float4*)(g_A + b * NN);
        const bool km1 = (cx & 4) == 0;
        const bool km2 = (cx & 2) == 0;
        const bool km3 = (cx & 1) == 0;
        #pragma unroll
        for (int g = 0; g < 2; g++) {
            const int o = t * 2 + g;
            float4 a0 = src[cx * 256 + o],       a1 = src[(cx ^ 1) * 256 + o];
            float4 a2 = src[(cx ^ 2) * 256 + o], a3 = src[(cx ^ 3) * 256 + o];
            float4 a4 = src[(cx ^ 4) * 256 + o], a5 = src[(cx ^ 5) * 256 + o];
            float4 a6 = src[(cx ^ 6) * 256 + o], a7 = src[(cx ^ 7) * 256 + o];
            float4 u0 = f4ce(a0, a4, km1), u2 = f4ce(a2, a6, km1);
            float4 u1 = f4ce(a1, a5, km1), u3 = f4ce(a3, a7, km1);
            float4 r  = f4ce(f4ce(u0, u2, km2), f4ce(u1, u3, km2), km3);
            v[g*4+0]=r.x; v[g*4+1]=r.y; v[g*4+2]=r.z; v[g*4+3]=r.w;
        }
        block_merge128(v, s4, t, true, 512);
        store8(g_B, b * NN + cx * 1024 + t * EPT, v);
    }
    grid_sync(phase);

    // ===== Phase E: K-window on chunk cx (halo +-19), g_B -> g_pack ==========
    {
        const float* __restrict__ src = g_B + b * NN;
        const int p0 = cx * 1024;
        for (int i = t; i < 1024 + 2 * (KNN - 1); i += 128) {
            int gg = p0 - (KNN - 1) + i;
            swin[i] = (gg >= 0 && gg < NN) ? src[gg] : 0.f;  // unread when OOB
        }
        __syncthreads();
        #define SW(li) swin[(li) + (KNN - 1)]
        int   lo[EPT], hi[EPT];
        float dl[EPT], dr[EPT], xv[EPT];
        #pragma unroll
        for (int m = 0; m < EPT; m++) {
            int l = t * EPT + m, p = p0 + l;
            xv[m] = SW(l);
            lo[m] = l; hi[m] = l;
            dl[m] = (p > 0)      ? (xv[m] - SW(l - 1)) : FLT_MAX;
            dr[m] = (p < NN - 1) ? (SW(l + 1) - xv[m]) : FLT_MAX;
        }
        for (int it = 1; it < KNN; it++) {
            #pragma unroll
            for (int m = 0; m < EPT; m++) {
                if (dl[m] <= dr[m]) {
                    lo[m]--;
                    dl[m] = (p0 + lo[m] > 0) ? (xv[m] - SW(lo[m] - 1)) : FLT_MAX;
                } else {
                    hi[m]++;
                    dr[m] = (p0 + hi[m] < NN - 1) ? (SW(hi[m] + 1) - xv[m]) : FLT_MAX;
                }
            }
        }
        float4* gp = g_pack + b * NN + p0;
        #pragma unroll
        for (int m = 0; m < EPT; m++) {
            int l = t * EPT + m;
            gp[l] = make_float4(xv[m], SW(lo[m]) - xv[m], SW(hi[m]) - xv[m], 0.f);
        }
        #undef SW
    }
    grid_sync(phase);

    // ===== Phase F: reduce 8 channels (o = cx*8 + e) + FC via atomics ========
    {
        const int obase = cx * 8;
        float w0[8], w1[8], scv[8], shv[8];
        #pragma unroll
        for (int e = 0; e < 8; e++) {
            int o = obase + e;
            w0[e]  = conv_w[o * 2 + 0];
            w1[e]  = conv_w[o * 2 + 1];
            scv[e] = gamma[o] * rsqrtf(var[o] + BN_EPS);
            shv[e] = beta[o] - mean[o] * scv[e];
        }
        float mx[8], sm[8];
        #pragma unroll
        for (int e = 0; e < 8; e++) { mx[e] = 0.f; sm[e] = 0.f; }

        const float4* __restrict__ gp = g_pack + b * NN;
        for (int p = t; p < NN; p += 128) {
            float4 q = gp[p];
            #pragma unroll
            for (int e = 0; e < 8; e++) {
                float ex = (scv[e] >= 0.f) ? fmaxf(w0[e] * q.y, w0[e] * q.z)
                                           : fminf(w0[e] * q.y, w0[e] * q.z);
                float h = fmaxf(fmaf(scv[e], fmaf(w1[e], q.x, ex), shv[e]), 0.f);
                mx[e] = fmaxf(mx[e], h);
                sm[e] += h;
            }
        }
        #pragma unroll
        for (int off = 16; off > 0; off >>= 1) {
            #pragma unroll
            for (int e = 0; e < 8; e++) {
                mx[e]  = fmaxf(mx[e], __shfl_xor_sync(0xffffffffu, mx[e], off));
                sm[e] += __shfl_xor_sync(0xffffffffu, sm[e], off);
            }
        }
        const int warp = t >> 5, lane = t & 31;
        if (lane == 0) {
            #pragma unroll
            for (int e = 0; e < 8; e++) { fx1[warp][e] = mx[e]; fx2[warp][e] = sm[e]; }
        }
        __syncthreads();
        if (t < 8) {
            float m0 = fmaxf(fmaxf(fx1[0][t], fx1[1][t]), fmaxf(fx1[2][t], fx1[3][t]));
            float s0 = fx2[0][t] + fx2[1][t] + fx2[2][t] + fx2[3][t];
            bx1[t] = m0;
            bx2[t] = s0 * (1.0f / NN);
        }
        __syncthreads();
        if (t < NCLASS) {
            const float* __restrict__ w = lin_w + t * (2 * COUT);
            float acc = 0.f;
            #pragma unroll
            for (int e = 0; e < 8; e++) {
                int o = obase + e;
                acc = fmaf(w[o], bx1[e], acc);
                acc = fmaf(w[COUT + o], bx2[e], acc);
            }
            atomicAdd(&out[b * NCLASS + t], acc);
        }
    }
}

// ---------------------------------------------------------------------------
extern "C" void kernel_launch(void* const* d_in, const int* in_sizes, int n_in,
                              void* d_out, int out_size) {
    const float* x      = (const float*)d_in[0];
    const float* conv_w = (const float*)d_in[1];
    const float* gamma  = (const float*)d_in[2];
    const float* beta   = (const float*)d_in[3];
    const float* mean   = (const float*)d_in[4];
    const float* var    = (const float*)d_in[5];
    const float* lin_w  = (const float*)d_in[6];
    float* out = (float*)d_out;

    k_all<<<dim3(8, NB), 128>>>(x, conv_w, gamma, beta, mean, var, lin_w, out);
}

// round 10
// speedup vs baseline: 1.7790x; 1.7790x over previous
#include <cuda_runtime.h>
#include <float.h>

#define NB     2
#define NN     8192
#define KNN    20
#define COUT   64
#define NCLASS 40
#define BN_EPS 1e-5f
#define EPT    8

// Scratch (no allocations allowed)
__device__ alignas(16) float  g_A[NB * NN];      // 8 ascending sorted 1024-runs
__device__ alignas(16) float4 g_pack[NB * NN];   // {x, dmin, dmax, 0} (run-permuted order)

// ---------------------------------------------------------------------------
// Compare-exchange helpers — ALL register indices compile-time constant.
// ---------------------------------------------------------------------------
__device__ __forceinline__ void ce(float& a, float& b, bool up) {
    float mn = fminf(a, b), mx = fmaxf(a, b);
    a = up ? mn : mx;
    b = up ? mx : mn;
}

__device__ __forceinline__ void reg_merge(float v[EPT], bool d) {
    ce(v[0], v[4], d); ce(v[1], v[5], d); ce(v[2], v[6], d); ce(v[3], v[7], d);
    ce(v[0], v[2], d); ce(v[1], v[3], d); ce(v[4], v[6], d); ce(v[5], v[7], d);
    ce(v[0], v[1], d); ce(v[2], v[3], d); ce(v[4], v[5], d); ce(v[6], v[7], d);
}

__device__ __forceinline__ void sort8(float v[EPT], bool d8) {
    ce(v[0], v[1], true);  ce(v[2], v[3], false);
    ce(v[4], v[5], true);  ce(v[6], v[7], false);
    ce(v[0], v[2], true);  ce(v[1], v[3], true);
    ce(v[4], v[6], false); ce(v[5], v[7], false);
    ce(v[0], v[1], true);  ce(v[2], v[3], true);
    ce(v[4], v[5], false); ce(v[6], v[7], false);
    reg_merge(v, d8);
}

__device__ __forceinline__ void warp_merge(float v[EPT], bool d, int xm_start, int t) {
    for (int xm = xm_start; xm >= 1; xm >>= 1) {
        bool lowup = (((t & xm) == 0) == d);
        #pragma unroll
        for (int m = 0; m < EPT; m++) {
            float pv = __shfl_xor_sync(0xffffffffu, v[m], xm);
            v[m] = lowup ? fminf(v[m], pv) : fmaxf(v[m], pv);
        }
    }
    reg_merge(v, d);
}

// smem substages j = jstart..256 (128-thread block), then intra-warp tail.
__device__ __forceinline__ void block_merge128(float v[EPT], float4* sA, int t,
                                               bool d, int jstart) {
    float4* sB = sA + 128;
    for (int j = jstart; j >= 256; j >>= 1) {
        sA[t] = make_float4(v[0], v[1], v[2], v[3]);
        sB[t] = make_float4(v[4], v[5], v[6], v[7]);
        __syncthreads();
        const int  pt    = t ^ (j >> 3);
        const bool lowup = (((t & (j >> 3)) == 0) == d);
        float4 pa = sA[pt], pb = sB[pt];
        v[0] = lowup ? fminf(v[0], pa.x) : fmaxf(v[0], pa.x);
        v[1] = lowup ? fminf(v[1], pa.y) : fmaxf(v[1], pa.y);
        v[2] = lowup ? fminf(v[2], pa.z) : fmaxf(v[2], pa.z);
        v[3] = lowup ? fminf(v[3], pa.w) : fmaxf(v[3], pa.w);
        v[4] = lowup ? fminf(v[4], pb.x) : fmaxf(v[4], pb.x);
        v[5] = lowup ? fminf(v[5], pb.y) : fmaxf(v[5], pb.y);
        v[6] = lowup ? fminf(v[6], pb.z) : fmaxf(v[6], pb.z);
        v[7] = lowup ? fminf(v[7], pb.w) : fmaxf(v[7], pb.w);
        __syncthreads();
    }
    warp_merge(v, d, 16, t);
}

// ---------------------------------------------------------------------------
// K1: sort each 1024-chunk ASCENDING (k = 2..1024). grid (8, NB) x 128 thr.
// Also zeroes d_out (poisoned by harness) for the atomic FC accumulation.
// ---------------------------------------------------------------------------
__global__ void __launch_bounds__(128, 1) k_sort1024(const float* __restrict__ x,
                                                     float* __restrict__ out) {
    __shared__ float4 s[256];
    const int t = threadIdx.x;
    const int b = blockIdx.y, cx = blockIdx.x;
    if (b == 0 && cx == 0 && t < NB * NCLASS) out[t] = 0.f;

    const float4* src = (const float4*)(x + b * NN + cx * 1024);
    float v[EPT];
    { float4 a = src[t * 2], c = src[t * 2 + 1];
      v[0]=a.x; v[1]=a.y; v[2]=a.z; v[3]=a.w;
      v[4]=c.x; v[5]=c.y; v[6]=c.z; v[7]=c.w; }

    sort8(v, (t & 1) == 0);                            // k = 2,4,8
    for (int k = 16; k <= 256; k <<= 1)                // k = 16..256
        warp_merge(v, (t & (k >> 3)) == 0, k >> 4, t);
    block_merge128(v, s, t, (t & 64) == 0, 256);       // k = 512
    block_merge128(v, s, t, true, 512);                // k = 1024 (ascending)

    float4* dst = (float4*)(g_A + b * NN + cx * 1024);
    dst[t * 2]     = make_float4(v[0], v[1], v[2], v[3]);
    dst[t * 2 + 1] = make_float4(v[4], v[5], v[6], v[7]);
}

// ---------------------------------------------------------------------------
// K2: 8-run K-window. grid (32, NB) x 256 threads, one point per thread.
// Whole batch (8 ascending runs, 32KB) in smem. For each point:
//   lower_bound into every run (10-step branchless search, 8 ILP chains),
//   then 19 greedy picks of the nearest remaining left/right candidate
//   across runs. Final window endpoints -> g_pack (order-permuted; reduce
//   is symmetric over points so order is irrelevant).
// ---------------------------------------------------------------------------
__global__ void __launch_bounds__(256, 1) k_window8() {
    __shared__ float s[NN];                 // 32KB
    const int t = threadIdx.x;
    const int b = blockIdx.y;
    const int pg = blockIdx.x * 256 + t;    // position = run*1024 + idx
    const int ro = pg >> 10;                // own run
    const int io = pg & 1023;               // own index within run

    { const float4* src = (const float4*)(g_A + b * NN);
      float4* s4 = (float4*)s;
      for (int j = t; j < NN / 4; j += 256) s4[j] = src[j];
    }
    __syncthreads();

    const float xv = s[pg];

    // lower_bound (count of elements < xv) in each run; interleaved for ILP.
    int pos[8];
    #pragma unroll
    for (int r = 0; r < 8; r++) pos[r] = 0;
    #pragma unroll
    for (int step = 512; step >= 1; step >>= 1) {
        #pragma unroll
        for (int r = 0; r < 8; r++)
            if (s[r * 1024 + pos[r] + step - 1] < xv) pos[r] += step;
    }
    #pragma unroll
    for (int r = 0; r < 8; r++)            // fix all-elements-smaller case
        if (s[r * 1024 + pos[r]] < xv) pos[r]++;

    // Per-run two-sided candidate pointers. Own run: self at io excluded
    // (it is the already-picked center, d = 0).
    int   L[8], R[8];
    float dl[8], dr[8];
    #pragma unroll
    for (int r = 0; r < 8; r++) {
        const bool own = (r == ro);
        L[r] = own ? (io - 1) : (pos[r] - 1);
        R[r] = own ? (io + 1) : pos[r];
        dl[r] = (L[r] >= 0)   ? (xv - s[r * 1024 + L[r]]) : FLT_MAX;
        dr[r] = (R[r] < 1024) ? (s[r * 1024 + R[r]] - xv) : FLT_MAX;
    }

    float dminv = 0.f, dmaxv = 0.f;
    for (int it = 1; it < KNN; it++) {      // 19 greedy picks (+ self = 20)
        float dlm = dl[0]; int bl = 0;
        #pragma unroll
        for (int r = 1; r < 8; r++) if (dl[r] < dlm) { dlm = dl[r]; bl = r; }
        float drm = dr[0]; int br = 0;
        #pragma unroll
        for (int r = 1; r < 8; r++) if (dr[r] < drm) { drm = dr[r]; br = r; }

        if (dlm <= drm) {
            dminv = -dlm;                   // left deltas are non-decreasing
            #pragma unroll
            for (int r = 0; r < 8; r++) if (r == bl) {
                L[r]--;
                dl[r] = (L[r] >= 0) ? (xv - s[r * 1024 + L[r]]) : FLT_MAX;
            }
        } else {
            dmaxv = drm;                    // right deltas are non-decreasing
            #pragma unroll
            for (int r = 0; r < 8; r++) if (r == br) {
                R[r]++;
                dr[r] = (R[r] < 1024) ? (s[r * 1024 + R[r]] - xv) : FLT_MAX;
            }
        }
    }

    g_pack[b * NN + pg] = make_float4(xv, dminv, dmaxv, 0.f);
}

// ---------------------------------------------------------------------------
// K3: reduce (max & mean per (batch,channel)) + fused FC via atomicAdd.
// ---------------------------------------------------------------------------
__global__ void __launch_bounds__(256) reduce_fc(const float* __restrict__ conv_w,
                                                 const float* __restrict__ gamma,
                                                 const float* __restrict__ beta,
                                                 const float* __restrict__ mean,
                                                 const float* __restrict__ var,
                                                 const float* __restrict__ lin_w,
                                                 float* __restrict__ out) {
    __shared__ float smx[8], ssm[8], bx1, bx2;
    const int b = blockIdx.x >> 6;
    const int o = blockIdx.x & 63;

    const float w0 = conv_w[o * 2 + 0];
    const float w1 = conv_w[o * 2 + 1];
    const float sc = gamma[o] * rsqrtf(var[o] + BN_EPS);
    const float sh = beta[o] - mean[o] * sc;
    const bool pos = (sc >= 0.f);

    const float4* __restrict__ gp = g_pack + b * NN;
    float mx = 0.f, sum = 0.f;
    #pragma unroll 4
    for (int p = threadIdx.x; p < NN; p += 256) {
        float4 q = gp[p];
        float e = pos ? fmaxf(w0 * q.y, w0 * q.z)
                      : fminf(w0 * q.y, w0 * q.z);
        float h = fmaxf(fmaf(sc, fmaf(w1, q.x, e), sh), 0.f);
        mx = fmaxf(mx, h);
        sum += h;
    }
    #pragma unroll
    for (int off = 16; off > 0; off >>= 1) {
        mx  = fmaxf(mx, __shfl_xor_sync(0xffffffffu, mx, off));
        sum += __shfl_xor_sync(0xffffffffu, sum, off);
    }
    const int warp = threadIdx.x >> 5, lane = threadIdx.x & 31;
    if (lane == 0) { smx[warp] = mx; ssm[warp] = sum; }
    __syncthreads();
    if (threadIdx.x == 0) {
        float fmx = smx[0], fsm = ssm[0];
        #pragma unroll
        for (int w = 1; w < 8; w++) { fmx = fmaxf(fmx, smx[w]); fsm += ssm[w]; }
        bx1 = fmx;
        bx2 = fsm * (1.0f / NN);
    }
    __syncthreads();
    if (threadIdx.x < NCLASS) {
        const int c = threadIdx.x;
        float contr = lin_w[c * (2 * COUT) + o]        * bx1
                    + lin_w[c * (2 * COUT) + COUT + o] * bx2;
        atomicAdd(&out[b * NCLASS + c], contr);
    }
}

// ---------------------------------------------------------------------------
extern "C" void kernel_launch(void* const* d_in, const int* in_sizes, int n_in,
                              void* d_out, int out_size) {
    const float* x      = (const float*)d_in[0];
    const float* conv_w = (const float*)d_in[1];
    const float* gamma  = (const float*)d_in[2];
    const float* beta   = (const float*)d_in[3];
    const float* mean   = (const float*)d_in[4];
    const float* var    = (const float*)d_in[5];
    const float* lin_w  = (const float*)d_in[6];
    float* out = (float*)d_out;

    k_sort1024<<<dim3(8, NB), 128>>>(x, out);     // x   -> g_A (8 asc runs)
    k_window8<<<dim3(NN / 256, NB), 256>>>();     // g_A -> g_pack
    reduce_fc<<<NB * COUT, 256>>>(conv_w, gamma, beta, mean, var, lin_w, out);
}

// round 11
// speedup vs baseline: 2.4965x; 1.4033x over previous
#include <cuda_runtime.h>
#include <float.h>

#define NB     2
#define NN     8192
#define KNN    20
#define COUT   64
#define NCLASS 40
#define BN_EPS 1e-5f
#define EPT    8

// Scratch (no allocations allowed)
__device__ alignas(16) float  g_A[NB * NN];      // post-k4096 chunks
__device__ alignas(16) float  g_B[NB * NN];      // post-k2048 chunks
__device__ alignas(16) float4 g_pack[NB * NN];   // {x, dmin, dmax, 0}

// ---------------------------------------------------------------------------
// Compare-exchange helpers — ALL register indices compile-time constant.
// Global bitonic rule: at stage k, element i merges ascending iff (i&k)==0.
// ---------------------------------------------------------------------------
__device__ __forceinline__ void ce(float& a, float& b, bool up) {
    float mn = fminf(a, b), mx = fmaxf(a, b);
    a = up ? mn : mx;
    b = up ? mx : mn;
}

__device__ __forceinline__ void reg_merge(float v[EPT], bool d) {
    ce(v[0], v[4], d); ce(v[1], v[5], d); ce(v[2], v[6], d); ce(v[3], v[7], d);
    ce(v[0], v[2], d); ce(v[1], v[3], d); ce(v[4], v[6], d); ce(v[5], v[7], d);
    ce(v[0], v[1], d); ce(v[2], v[3], d); ce(v[4], v[5], d); ce(v[6], v[7], d);
}

__device__ __forceinline__ void sort8(float v[EPT], bool d8) {
    ce(v[0], v[1], true);  ce(v[2], v[3], false);
    ce(v[4], v[5], true);  ce(v[6], v[7], false);
    ce(v[0], v[2], true);  ce(v[1], v[3], true);
    ce(v[4], v[6], false); ce(v[5], v[7], false);
    ce(v[0], v[1], true);  ce(v[2], v[3], true);
    ce(v[4], v[5], false); ce(v[6], v[7], false);
    reg_merge(v, d8);
}

__device__ __forceinline__ void warp_merge(float v[EPT], bool d, int xm_start, int u) {
    for (int xm = xm_start; xm >= 1; xm >>= 1) {
        bool lowup = (((u & xm) == 0) == d);
        #pragma unroll
        for (int m = 0; m < EPT; m++) {
            float pv = __shfl_xor_sync(0xffffffffu, v[m], xm);
            v[m] = lowup ? fminf(v[m], pv) : fmaxf(v[m], pv);
        }
    }
    reg_merge(v, d);
}

// Subgroup-local merge over a 1024-element chunk held by 128 threads.
// sA = this subgroup's 256-float4 smem region; u = thread id in subgroup.
// __syncthreads is block-wide — ALL subgroups call with identical stage counts.
__device__ __forceinline__ void sub_merge(float v[EPT], float4* sA, int u,
                                          bool d, int jstart) {
    float4* sB = sA + 128;
    for (int j = jstart; j >= 256; j >>= 1) {
        sA[u] = make_float4(v[0], v[1], v[2], v[3]);
        sB[u] = make_float4(v[4], v[5], v[6], v[7]);
        __syncthreads();
        const int  pt    = u ^ (j >> 3);
        const bool lowup = (((u & (j >> 3)) == 0) == d);
        float4 pa = sA[pt], pb = sB[pt];
        v[0] = lowup ? fminf(v[0], pa.x) : fmaxf(v[0], pa.x);
        v[1] = lowup ? fminf(v[1], pa.y) : fmaxf(v[1], pa.y);
        v[2] = lowup ? fminf(v[2], pa.z) : fmaxf(v[2], pa.z);
        v[3] = lowup ? fminf(v[3], pa.w) : fmaxf(v[3], pa.w);
        v[4] = lowup ? fminf(v[4], pb.x) : fmaxf(v[4], pb.x);
        v[5] = lowup ? fminf(v[5], pb.y) : fmaxf(v[5], pb.y);
        v[6] = lowup ? fminf(v[6], pb.z) : fmaxf(v[6], pb.z);
        v[7] = lowup ? fminf(v[7], pb.w) : fmaxf(v[7], pb.w);
        __syncthreads();
    }
    warp_merge(v, d, 16, u);
}

__device__ __forceinline__ float4 f4ce(float4 a, float4 b, bool mn) {
    float4 r;
    r.x = mn ? fminf(a.x, b.x) : fmaxf(a.x, b.x);
    r.y = mn ? fminf(a.y, b.y) : fmaxf(a.y, b.y);
    r.z = mn ? fminf(a.z, b.z) : fmaxf(a.z, b.z);
    r.w = mn ? fminf(a.w, b.w) : fmaxf(a.w, b.w);
    return r;
}

// ---------------------------------------------------------------------------
// K1: fused sort (k<=1024) + k=2048 merge. grid (8, NB) x 256 threads.
// Block cx outputs post-k2048 chunk cx. Subgroup g sorts chunk cs=(cx&~1)|g
// (both pair chunks sorted in parallel, 2x redundant across blocks); the
// k=2048 butterfly reads the partner chunk from smem; each subgroup locally
// merges its own cs; only the subgroup with cs==cx stores.
// Also zeroes d_out (poisoned by harness) for the atomic FC accumulation.
// ---------------------------------------------------------------------------
__global__ void __launch_bounds__(256, 1) k_sortm1(const float* __restrict__ x,
                                                   float* __restrict__ out) {
    __shared__ float4 sm[2 * 256];          // 2 chunk regions, 8KB
    const int t = threadIdx.x;
    const int cx = blockIdx.x, b = blockIdx.y;
    const int g = t >> 7, u = t & 127;
    const int cs = (cx & ~1) | g;           // chunk this subgroup processes
    if (b == 0 && cx == 0 && t < NB * NCLASS) out[t] = 0.f;

    float4* reg = sm + g * 256;

    float v[EPT];
    { const float4* src = (const float4*)(x + b * NN + cs * 1024);
      float4 a = src[u * 2], c = src[u * 2 + 1];
      v[0]=a.x; v[1]=a.y; v[2]=a.z; v[3]=a.w;
      v[4]=c.x; v[5]=c.y; v[6]=c.z; v[7]=c.w; }

    // k = 2..1024 (chunk-local, proven path)
    sort8(v, (u & 1) == 0);
    for (int k = 16; k <= 256; k <<= 1)
        warp_merge(v, (u & (k >> 3)) == 0, k >> 4, u);
    sub_merge(v, reg, u, (u & 64) == 0, 256);      // k = 512
    sub_merge(v, reg, u, (cs & 1) == 0, 512);      // k = 1024

    // k = 2048: butterfly vs partner chunk (smem), then local j<=512 merge.
    const bool asc = ((cs >> 1) & 1) == 0;         // same for both subgroups
    const bool km1 = asc == ((cs & 1) == 0);
    reg[u * 2]     = make_float4(v[0], v[1], v[2], v[3]);
    reg[u * 2 + 1] = make_float4(v[4], v[5], v[6], v[7]);
    __syncthreads();
    { const float4* pr = sm + (g ^ 1) * 256;
      float4 pa = pr[u * 2], pb = pr[u * 2 + 1];
      float4 ra = f4ce(make_float4(v[0], v[1], v[2], v[3]), pa, km1);
      float4 rb = f4ce(make_float4(v[4], v[5], v[6], v[7]), pb, km1);
      v[0]=ra.x; v[1]=ra.y; v[2]=ra.z; v[3]=ra.w;
      v[4]=rb.x; v[5]=rb.y; v[6]=rb.z; v[7]=rb.w; }
    __syncthreads();
    sub_merge(v, reg, u, asc, 512);

    if (g == (cx & 1)) {                           // this subgroup holds chunk cx
        float4* dst = (float4*)(g_B + b * NN + cx * 1024);
        dst[u * 2]     = make_float4(v[0], v[1], v[2], v[3]);
        dst[u * 2 + 1] = make_float4(v[4], v[5], v[6], v[7]);
    }
}

// ---------------------------------------------------------------------------
// K2: k = 4096 stage — j=2048,1024 butterfly at load + local j<=512.
// grid (8, NB) x 128 threads. g_B -> g_A. (Proven in R7.)
// ---------------------------------------------------------------------------
__global__ void __launch_bounds__(128, 1) k_merge2() {
    __shared__ float4 s[256];
    const int t = threadIdx.x;
    const int cx = blockIdx.x, b = blockIdx.y;
    const float4* src = (const float4*)(g_B + b * NN);

    const bool asc = ((cx >> 2) & 1) == 0;
    const bool km1 = asc == (((cx >> 1) & 1) == 0);
    const bool km2 = asc == ((cx & 1) == 0);

    float v[EPT];
    #pragma unroll
    for (int g = 0; g < 2; g++) {
        const int o = t * 2 + g;
        float4 a0 = src[cx * 256 + o],       a1 = src[(cx ^ 1) * 256 + o];
        float4 a2 = src[(cx ^ 2) * 256 + o], a3 = src[(cx ^ 3) * 256 + o];
        float4 r = f4ce(f4ce(a0, a2, km1), f4ce(a1, a3, km1), km2);
        v[g*4+0]=r.x; v[g*4+1]=r.y; v[g*4+2]=r.z; v[g*4+3]=r.w;
    }

    sub_merge(v, s, t, asc, 512);

    float4* dst = (float4*)(g_A + b * NN + cx * 1024);
    dst[t * 2]     = make_float4(v[0], v[1], v[2], v[3]);
    dst[t * 2 + 1] = make_float4(v[4], v[5], v[6], v[7]);
}

// ---------------------------------------------------------------------------
// K3: final k=8192 merge + K-window, fused. grid (8, NB) x 384 thr.
// Subgroup g in {0,1,2} computes final sorted chunk cx+g-1 (clamped; edge
// duplicates harmless) -> 3-chunk contiguous span in smem; then the window
// for middle chunk cx runs with its +-19 halo already resident.
// (Proven in R8.)
// ---------------------------------------------------------------------------
__global__ void __launch_bounds__(384, 1) k_merge3win() {
    __shared__ float smf[3 * 1024];
    float4* sm4 = (float4*)smf;
    const int t = threadIdx.x;
    const int cx = blockIdx.x, b = blockIdx.y;
    const int g = t / 128, u = t & 127;
    int c = cx + g - 1;
    c = (c < 0) ? 0 : ((c > 7) ? 7 : c);

    const bool km1 = (c & 4) == 0;
    const bool km2 = (c & 2) == 0;
    const bool km3 = (c & 1) == 0;

    const float4* src = (const float4*)(g_A + b * NN);
    float v[EPT];
    #pragma unroll
    for (int h = 0; h < 2; h++) {
        const int o = u * 2 + h;
        float4 a0 = src[c * 256 + o],       a1 = src[(c ^ 1) * 256 + o];
        float4 a2 = src[(c ^ 2) * 256 + o], a3 = src[(c ^ 3) * 256 + o];
        float4 a4 = src[(c ^ 4) * 256 + o], a5 = src[(c ^ 5) * 256 + o];
        float4 a6 = src[(c ^ 6) * 256 + o], a7 = src[(c ^ 7) * 256 + o];
        float4 u0 = f4ce(a0, a4, km1), u2 = f4ce(a2, a6, km1);
        float4 u1 = f4ce(a1, a5, km1), u3 = f4ce(a3, a7, km1);
        float4 r  = f4ce(f4ce(u0, u2, km2), f4ce(u1, u3, km2), km3);
        v[h*4+0] = r.x; v[h*4+1] = r.y; v[h*4+2] = r.z; v[h*4+3] = r.w;
    }

    sub_merge(v, sm4 + g * 256, u, true, 512);

    { float4* nat = sm4 + g * 256;
      nat[u * 2]     = make_float4(v[0], v[1], v[2], v[3]);
      nat[u * 2 + 1] = make_float4(v[4], v[5], v[6], v[7]); }
    __syncthreads();

    // window for middle chunk: 3 interleaved expansions per thread.
    const int off = 1024 - cx * 1024;     // smem index of global pos p is p+off
    int   pl[3];
    pl[0] = t; pl[1] = t + 384;
    const bool v2 = (t + 768) < 1024;
    pl[2] = v2 ? (t + 768) : 1023;

    float xv[3], dl[3], dr[3];
    int lo[3], hi[3];
    #pragma unroll
    for (int e = 0; e < 3; e++) {
        int p = cx * 1024 + pl[e];
        lo[e] = p; hi[e] = p;
        xv[e] = smf[p + off];
        dl[e] = (p > 0)      ? (xv[e] - smf[p - 1 + off]) : FLT_MAX;
        dr[e] = (p < NN - 1) ? (smf[p + 1 + off] - xv[e]) : FLT_MAX;
    }
    for (int it = 1; it < KNN; it++) {
        #pragma unroll
        for (int e = 0; e < 3; e++) {
            if (dl[e] <= dr[e]) {
                lo[e]--;
                dl[e] = (lo[e] > 0) ? (xv[e] - smf[lo[e] - 1 + off]) : FLT_MAX;
            } else {
                hi[e]++;
                dr[e] = (hi[e] < NN - 1) ? (smf[hi[e] + 1 + off] - xv[e]) : FLT_MAX;
            }
        }
    }
    #pragma unroll
    for (int e = 0; e < 3; e++) {
        if (e == 2 && !v2) break;
        int p = cx * 1024 + pl[e];
        g_pack[b * NN + p] = make_float4(xv[e],
                                         smf[lo[e] + off] - xv[e],
                                         smf[hi[e] + off] - xv[e], 0.f);
    }
}

// ---------------------------------------------------------------------------
// K4: reduce (max & mean per (batch,channel)) + fused FC via atomicAdd.
// ---------------------------------------------------------------------------
__global__ void __launch_bounds__(256) reduce_fc(const float* __restrict__ conv_w,
                                                 const float* __restrict__ gamma,
                                                 const float* __restrict__ beta,
                                                 const float* __restrict__ mean,
                                                 const float* __restrict__ var,
                                                 const float* __restrict__ lin_w,
                                                 float* __restrict__ out) {
    __shared__ float smx[8], ssm[8], bx1, bx2;
    const int b = blockIdx.x >> 6;
    const int o = blockIdx.x & 63;

    const float w0 = conv_w[o * 2 + 0];
    const float w1 = conv_w[o * 2 + 1];
    const float sc = gamma[o] * rsqrtf(var[o] + BN_EPS);
    const float sh = beta[o] - mean[o] * sc;
    const bool pos = (sc >= 0.f);

    const float4* __restrict__ gp = g_pack + b * NN;
    float mx = 0.f, sum = 0.f;
    #pragma unroll 4
    for (int p = threadIdx.x; p < NN; p += 256) {
        float4 q = gp[p];
        float e = pos ? fmaxf(w0 * q.y, w0 * q.z)
                      : fminf(w0 * q.y, w0 * q.z);
        float h = fmaxf(fmaf(sc, fmaf(w1, q.x, e), sh), 0.f);
        mx = fmaxf(mx, h);
        sum += h;
    }
    #pragma unroll
    for (int off = 16; off > 0; off >>= 1) {
        mx  = fmaxf(mx, __shfl_xor_sync(0xffffffffu, mx, off));
        sum += __shfl_xor_sync(0xffffffffu, sum, off);
    }
    const int warp = threadIdx.x >> 5, lane = threadIdx.x & 31;
    if (lane == 0) { smx[warp] = mx; ssm[warp] = sum; }
    __syncthreads();
    if (threadIdx.x == 0) {
        float fmx = smx[0], fsm = ssm[0];
        #pragma unroll
        for (int w = 1; w < 8; w++) { fmx = fmaxf(fmx, smx[w]); fsm += ssm[w]; }
        bx1 = fmx;
        bx2 = fsm * (1.0f / NN);
    }
    __syncthreads();
    if (threadIdx.x < NCLASS) {
        const int c = threadIdx.x;
        float contr = lin_w[c * (2 * COUT) + o]        * bx1
                    + lin_w[c * (2 * COUT) + COUT + o] * bx2;
        atomicAdd(&out[b * NCLASS + c], contr);
    }
}

// ---------------------------------------------------------------------------
extern "C" void kernel_launch(void* const* d_in, const int* in_sizes, int n_in,
                              void* d_out, int out_size) {
    const float* x      = (const float*)d_in[0];
    const float* conv_w = (const float*)d_in[1];
    const float* gamma  = (const float*)d_in[2];
    const float* beta   = (const float*)d_in[3];
    const float* mean   = (const float*)d_in[4];
    const float* var    = (const float*)d_in[5];
    const float* lin_w  = (const float*)d_in[6];
    float* out = (float*)d_out;

    k_sortm1<<<dim3(8, NB), 256>>>(x, out);     // x   -> g_B (k <= 2048)
    k_merge2<<<dim3(8, NB), 128>>>();           // g_B -> g_A (k = 4096)
    k_merge3win<<<dim3(8, NB), 384>>>();        // g_A -> g_pack (k=8192 + window)
    reduce_fc<<<NB * COUT, 256>>>(conv_w, gamma, beta, mean, var, lin_w, out);
}